// round 17
// baseline (speedup 1.0000x reference)
#include <cuda_runtime.h>
#include <cuda_bf16.h>
#include <cstdint>

// ============================================================================
// TNLayer, round 17: R16 base (best: 52.2us) + half-tile cp.async groups.
// The 32-row A prefetch is split into two 16-row commit-groups; sub-tiles are
// processed sequentially, each waiting only for its own half (wait_group<1>)
// and re-issuing that half for the next tile immediately after its fragment
// reads. Compute starts ~0.5 tile earlier, next-tile loads issue ~0.5 tile
// earlier, LDG issue is smoothed. Streaming (__stcs) output stores.
//
//  h0[n,b]   = sum_i x0[n,i] t0[i,b]              (GEMM1: N=16, K=32)
//  h1[n,b,o] = sum_j x1[n,j] t1[j,b,o]            (GEMM2: N=104, K=32)
//  c[n,o]    = sum_b h0 * h1 + bias[o]; sigmoid
//
// B1 fragment-major blocks e = 0..12:
//   e = 0..9  : b=e, o=g                (thread-local epilogue)
//   e = 10+q  : b=4q+(g>>1), o=8+(g&1)  (quad bfly reduce)
// fragment word wd of lane (g,t): j pair (2t+8wd, 2t+8wd+1), zero for j>=28.
// A overflow reads (k>=56) land in the next dense row (possibly mid-refill:
// still a finite float) or the zeroed 16B guard, and multiply zero B slots
// -> contribute exactly 0.
// ============================================================================

#define NTHREADS 128
#define NTILES   8192             // 1048576 / 128
#define GRID_X   592              // 148 SMs * 4 persistent CTAs
#define A_STRIDE 224              // bytes per A row = 56 f32, dense
#define A_BUF    (32 * A_STRIDE)  // 7168 B single stage per warp
#define SBF_OFF  (4 * A_BUF + 16) // 16B zero guard after A region
#define SMEM_TOTAL (SBF_OFF + 13 * 512)   // 35344

static __device__ __forceinline__ uint32_t smem_u32(const void* p) {
    uint32_t a;
    asm("{ .reg .u64 t; cvta.to.shared.u64 t, %1; cvt.u32.u64 %0, t; }"
        : "=r"(a) : "l"(p));
    return a;
}
static __device__ __forceinline__ void cp_async16(uint32_t dst, const void* src) {
    asm volatile("cp.async.cg.shared.global [%0], [%1], 16;" :: "r"(dst), "l"(src));
}
static __device__ __forceinline__ void cp_commit() {
    asm volatile("cp.async.commit_group;" ::: "memory");
}
template <int N> static __device__ __forceinline__ void cp_wait() {
    asm volatile("cp.async.wait_group %0;" :: "n"(N) : "memory");
}
static __device__ __forceinline__ void mma_bf16(float& c0, float& c1, float& c2, float& c3,
                                                uint32_t a0, uint32_t a1, uint32_t a2, uint32_t a3,
                                                uint32_t b0, uint32_t b1) {
    asm volatile(
        "mma.sync.aligned.m16n8k16.row.col.f32.bf16.bf16.f32 "
        "{%0,%1,%2,%3}, {%4,%5,%6,%7}, {%8,%9}, {%0,%1,%2,%3};"
        : "+f"(c0), "+f"(c1), "+f"(c2), "+f"(c3)
        : "r"(a0), "r"(a1), "r"(a2), "r"(a3), "r"(b0), "r"(b1));
}
static __device__ __forceinline__ uint32_t packbf(float lo, float hi) {
    __nv_bfloat162 p = __floats2bfloat162_rn(lo, hi);
    return *reinterpret_cast<uint32_t*>(&p);
}
static __device__ __forceinline__ float sigmoidf_(float c) {
    return __fdividef(1.0f, 1.0f + __expf(-c));
}

__global__ void __launch_bounds__(NTHREADS, 4)
tn_kernel(const float* __restrict__ x,
          const float* __restrict__ t0,
          const float* __restrict__ t1,
          const float* __restrict__ bias,
          float* __restrict__ out)
{
    __shared__ __align__(16) uint8_t smem[SMEM_TOTAL];
    uint8_t* sBf = smem + SBF_OFF;

    const int tid  = threadIdx.x;
    const int lane = tid & 31;
    const int w    = tid >> 5;
    const int g    = lane >> 2;     // 0..7
    const int t    = lane & 3;      // 0..3
    const int r0   = w * 32;

    // ---------------- one-time setup ----------------
    for (int i = tid; i < SBF_OFF / 4; i += NTHREADS)
        ((uint32_t*)smem)[i] = 0u;

    // B1 fragment-major fill: word wd -> j0 = 2*tt + 8*wd
    for (int idx = tid; idx < 13 * 128; idx += NTHREADS) {
        int e = idx >> 7, ln = (idx >> 2) & 31, wd = idx & 3;
        int gg = ln >> 2, tt = ln & 3;
        int j0 = 2 * tt + 8 * wd;
        int b, o;
        if (e < 10) { b = e; o = gg; }
        else        { int q = e - 10; b = 4 * q + (gg >> 1); o = 8 + (gg & 1); }
        float f0 = 0.f, f1 = 0.f;
        if (b < 10) {
            if (j0 < 28)     f0 = t1[j0 * 100 + b * 10 + o];
            if (j0 + 1 < 28) f1 = t1[(j0 + 1) * 100 + b * 10 + o];
        }
        ((uint32_t*)sBf)[idx] = packbf(f0, f1);
    }

    // B0 fragments in registers (k = 2t + 16kb + {0,1,8,9})
    auto T0 = [&](int i, int b) -> float {
        return (i < 28 && b < 10) ? __ldg(t0 + i * 10 + b) : 0.f;
    };
    uint32_t gb[2][2], fb[2][2];
#pragma unroll
    for (int kb = 0; kb < 2; kb++) {
        int k = 2 * t + 16 * kb;
        gb[kb][0] = packbf(T0(k, g),     T0(k + 1, g));
        gb[kb][1] = packbf(T0(k + 8, g), T0(k + 9, g));
        fb[kb][0] = packbf(T0(k, 8 + g),     T0(k + 1, 8 + g));
        fb[kb][1] = packbf(T0(k + 8, 8 + g), T0(k + 9, 8 + g));
    }
    const float bs0 = __ldg(bias + 2 * t);
    const float bs1 = __ldg(bias + 2 * t + 1);
    const float bs8 = __ldg(bias + 8);
    const float bs9 = __ldg(bias + 9);
    __syncthreads();

    uint8_t* aW = smem + w * A_BUF;
    const uint32_t aWu = smem_u32(aW);

    // half-tile prefetch: 16 rows = 224 float4 (7 per lane), linear.
    // ALWAYS commits (possibly empty) so wait_group<1> counts stay exact.
    auto prefetch_half = [&](int tl, int half) {
        if (tl < NTILES) {
            const float4* src = (const float4*)x + (size_t)tl * 1792 + r0 * 14;
#pragma unroll
            for (int i = 0; i < 7; i++) {
                int idx = lane + (half * 7 + i) * 32;   // 0..223 / 224..447
                cp_async16(aWu + idx * 16, src + idx);
            }
        }
        cp_commit();
    };

    int tile = blockIdx.x;
    prefetch_half(tile, 0);
    prefetch_half(tile, 1);      // 2 groups pending: [cur.h0, cur.h1]

    // ---------------- warp-independent tile loop ----------------
    for (; tile < NTILES; tile += GRID_X) {
        const int nt = tile + GRID_X;
        const int c0i = 2 * t;

#pragma unroll 1
        for (int s = 0; s < 2; s++) {
            // wait for this sub's half only (one group retired)
            cp_wait<1>();
            __syncwarp();

            const float* Ag = (const float*)(aW + (s * 16 + g) * A_STRIDE);
            const float* Ah = (const float*)(aW + (s * 16 + g + 8) * A_STRIDE);

            // ---- A fragments + GEMM1 (B in registers) ----
            float eA[4] = {0, 0, 0, 0};   // h0 cols 0..7  (b = 2t,2t+1)
            float fA[4] = {0, 0, 0, 0};   // h0 cols 8..15 (b = 8+2t)
            uint32_t xa[2][4];            // h1 A frags [kb][slot]
#pragma unroll
            for (int kb = 0; kb < 2; kb++) {
                const int k0 = c0i + 16 * kb;
                float2 v0 = *(const float2*)(Ag + k0);
                float2 v1 = *(const float2*)(Ah + k0);
                float2 v2 = *(const float2*)(Ag + k0 + 8);
                float2 v3 = *(const float2*)(Ah + k0 + 8);
                uint32_t a0 = packbf(v0.x, v0.y);
                uint32_t a1 = packbf(v1.x, v1.y);
                uint32_t a2 = packbf(v2.x, v2.y);
                uint32_t a3 = packbf(v3.x, v3.y);
                mma_bf16(eA[0], eA[1], eA[2], eA[3],
                         a0, a1, a2, a3, gb[kb][0], gb[kb][1]);
                mma_bf16(fA[0], fA[1], fA[2], fA[3],
                         a0, a1, a2, a3, fb[kb][0], fb[kb][1]);
                const int k1 = k0 + 28;   // overflow -> zero-B slots (finite)
                float2 w0 = *(const float2*)(Ag + k1);
                float2 w1 = *(const float2*)(Ah + k1);
                float2 w2 = *(const float2*)(Ag + k1 + 8);
                float2 w3 = *(const float2*)(Ah + k1 + 8);
                xa[kb][0] = packbf(w0.x, w0.y);
                xa[kb][1] = packbf(w1.x, w1.y);
                xa[kb][2] = packbf(w2.x, w2.y);
                xa[kb][3] = packbf(w3.x, w3.y);
            }

            // this half's smem reads are done: re-issue it for the next tile
            prefetch_half(nt, s);

            // ---- GEMM2 even blocks (B1 LDS.128), thread-local contraction ----
            float pA[4] = {0, 0, 0, 0};
#pragma unroll
            for (int e = 0; e < 10; e++) {
                uint4 bv = *(const uint4*)(sBf + e * 512 + lane * 16);
                float c0 = 0, c1 = 0, c2 = 0, c3 = 0;
                mma_bf16(c0, c1, c2, c3,
                         xa[0][0], xa[0][1], xa[0][2], xa[0][3], bv.x, bv.y);
                mma_bf16(c0, c1, c2, c3,
                         xa[1][0], xa[1][1], xa[1][2], xa[1][3], bv.z, bv.w);
                float h0g_e, h0h_e;
                if (e < 8) {
                    h0g_e = __shfl_sync(0xffffffffu, (e & 1) ? eA[1] : eA[0], e >> 1, 4);
                    h0h_e = __shfl_sync(0xffffffffu, (e & 1) ? eA[3] : eA[2], e >> 1, 4);
                } else {
                    h0g_e = __shfl_sync(0xffffffffu, (e & 1) ? fA[1] : fA[0], 0, 4);
                    h0h_e = __shfl_sync(0xffffffffu, (e & 1) ? fA[3] : fA[2], 0, 4);
                }
                pA[0] = fmaf(h0g_e, c0, pA[0]);
                pA[1] = fmaf(h0g_e, c1, pA[1]);
                pA[2] = fmaf(h0h_e, c2, pA[2]);
                pA[3] = fmaf(h0h_e, c3, pA[3]);
            }

            // ---- GEMM2 o89 blocks: b = 4q + t, quad bfly reduce ----
            float p89[4] = {0, 0, 0, 0};
#pragma unroll
            for (int q = 0; q < 3; q++) {
                uint4 bv = *(const uint4*)(sBf + (10 + q) * 512 + lane * 16);
                float c0 = 0, c1 = 0, c2 = 0, c3 = 0;
                mma_bf16(c0, c1, c2, c3,
                         xa[0][0], xa[0][1], xa[0][2], xa[0][3], bv.x, bv.y);
                mma_bf16(c0, c1, c2, c3,
                         xa[1][0], xa[1][1], xa[1][2], xa[1][3], bv.z, bv.w);
                const int srcl = 2 * q + (t >> 1);
                float v0 = __shfl_sync(0xffffffffu, eA[0], srcl, 4);
                float v1 = __shfl_sync(0xffffffffu, eA[1], srcl, 4);
                float v2 = __shfl_sync(0xffffffffu, eA[2], srcl, 4);
                float v3 = __shfl_sync(0xffffffffu, eA[3], srcl, 4);
                float vg = (t & 1) ? v1 : v0;
                float vh = (t & 1) ? v3 : v2;
                p89[0] = fmaf(vg, c0, p89[0]);
                p89[1] = fmaf(vg, c1, p89[1]);
                p89[2] = fmaf(vh, c2, p89[2]);
                p89[3] = fmaf(vh, c3, p89[3]);
            }
#pragma unroll
            for (int u = 0; u < 4; u++) {
                p89[u] += __shfl_xor_sync(0xffffffffu, p89[u], 1);
                p89[u] += __shfl_xor_sync(0xffffffffu, p89[u], 2);
            }

            // ---- sigmoid + streaming store ----
            float* og = out + ((size_t)tile * 128 + r0 + s * 16 + g) * 10;
            __stcs((float2*)(og + 2 * t),
                   make_float2(sigmoidf_(pA[0] + bs0), sigmoidf_(pA[1] + bs1)));
            __stcs((float2*)(og + 80 + 2 * t),
                   make_float2(sigmoidf_(pA[2] + bs0), sigmoidf_(pA[3] + bs1)));
            if (t == 0) {
                __stcs((float2*)(og + 8),
                       make_float2(sigmoidf_(p89[0] + bs8), sigmoidf_(p89[1] + bs9)));
                __stcs((float2*)(og + 88),
                       make_float2(sigmoidf_(p89[2] + bs8), sigmoidf_(p89[3] + bs9)));
            }
        }
    }
}

extern "C" void kernel_launch(void* const* d_in, const int* in_sizes, int n_in,
                              void* d_out, int out_size) {
    const float* x    = (const float*)d_in[0];
    const float* t0   = (const float*)d_in[1];
    const float* t1   = (const float*)d_in[2];
    const float* bias = (const float*)d_in[3];
    float* out = (float*)d_out;
    tn_kernel<<<GRID_X, NTHREADS>>>(x, t0, t1, bias, out);
}